// round 1
// baseline (speedup 1.0000x reference)
#include <cuda_runtime.h>

// Problem constants
#define SEQ    4096
#define BATCH  4
#define NLW    50        // LW
#define HALO   26        // max |m+n| under |m*n|<=25 constraint
#define TILE   32        // l-positions per block
#define SPLIT  4         // n-loop split factor (threadIdx.y)
#define SPOS   (TILE + 2*HALO)   // 84 smem positions
#define NS     449       // |S|
#define OUTL   (SEQ - 2*NLW)     // 3996

// nm(m) = max |n| for each m (m = idx-25): |m*n| <= 25
__constant__ int c_NM[51] = {
    1,1,1,1,1,1,1,1,1,1,1,1,1,   // m = -25..-13
    2,2,2,2,                     // m = -12..-9
    3,3,                         // m = -8,-7
    4,5,6,8,12,25,               // m = -6..-1
    25,                          // m = 0
    25,12,8,6,5,4,               // m = 1..6
    3,3,                         // m = 7,8
    2,2,2,2,                     // m = 9..12
    1,1,1,1,1,1,1,1,1,1,1,1,1    // m = 13..25
};

// Scratch: E1 and E1_mid (Ps-scaled), mode-packed (float2 = {mode0, mode1})
__device__ float2 g_E1r[BATCH*SEQ];
__device__ float2 g_E1i[BATCH*SEQ];
__device__ float2 g_Mr [BATCH*SEQ];
__device__ float2 g_Mi [BATCH*SEQ];

// ---------------------------------------------------------------------------
// Stage 1: E1[l] = Ps * sum_s w1_s * E[l-m] E[l-n] conj(E[l-m-n])
//          E1m[l] = same with w2   (triplet computed once, two accumulations)
// ---------------------------------------------------------------------------
__global__ void __launch_bounds__(TILE*SPLIT)
stage1_kernel(const float2* __restrict__ Er, const float2* __restrict__ Ei,
              const float*  __restrict__ task,
              const float*  __restrict__ w1r, const float* __restrict__ w1i,
              const float*  __restrict__ w2r, const float* __restrict__ w2i)
{
    __shared__ float2 sEr[SPOS], sEi[SPOS];
    __shared__ float4 sW[NS];                       // {w1r, w1i, w2r, w2i}
    __shared__ float4 sR1[SPLIT-1][TILE];
    __shared__ float4 sR2[SPLIT-1][TILE];

    const int tile = blockIdx.x, b = blockIdx.y;
    const int tx = threadIdx.x, ty = threadIdx.y;
    const int tid = ty * TILE + tx;
    const int base = tile * TILE;
    const float2* Erb = Er + b * SEQ;
    const float2* Eib = Ei + b * SEQ;

    for (int i = tid; i < SPOS; i += TILE*SPLIT) {
        int p = (base - HALO + i) & (SEQ - 1);
        sEr[i] = Erb[p];
        sEi[i] = Eib[p];
    }
    for (int s = tid; s < NS; s += TILE*SPLIT)
        sW[s] = make_float4(w1r[s], w1i[s], w2r[s], w2i[s]);
    __syncthreads();

    const int li = tx + HALO;
    float2 a1r = make_float2(0.f,0.f), a1i = make_float2(0.f,0.f);
    float2 a2r = make_float2(0.f,0.f), a2i = make_float2(0.f,0.f);

    int s0 = 0;
    #pragma unroll 1
    for (int mi = 0; mi < 51; ++mi) {
        const int m  = mi - 25;
        const int nm = c_NM[mi];
        const int g  = 2*nm + 1;
        const int lia = li - m;
        const float2 ar = sEr[lia], ai = sEi[lia];
        int lib = li  + nm - ty;     // l - n, n = -nm + k
        int lic = lia + nm - ty;     // l - m - n
        for (int k = ty; k < g; k += SPLIT, lib -= SPLIT, lic -= SPLIT) {
            const float2 br = sEr[lib], bi = sEi[lib];
            const float2 cr = sEr[lic], ci = sEi[lic];
            // u = a*b
            float2 ur, ui, tr, ti;
            ur.x = ar.x*br.x - ai.x*bi.x;  ur.y = ar.y*br.y - ai.y*bi.y;
            ui.x = ar.x*bi.x + ai.x*br.x;  ui.y = ar.y*bi.y + ai.y*br.y;
            // t = u*conj(c)
            tr.x = ur.x*cr.x + ui.x*ci.x;  tr.y = ur.y*cr.y + ui.y*ci.y;
            ti.x = ui.x*cr.x - ur.x*ci.x;  ti.y = ui.y*cr.y - ur.y*ci.y;
            const float4 w = sW[s0 + k];
            a1r.x += w.x*tr.x - w.y*ti.x;  a1r.y += w.x*tr.y - w.y*ti.y;
            a1i.x += w.x*ti.x + w.y*tr.x;  a1i.y += w.x*ti.y + w.y*tr.y;
            a2r.x += w.z*tr.x - w.w*ti.x;  a2r.y += w.z*tr.y - w.w*ti.y;
            a2i.x += w.z*ti.x + w.w*tr.x;  a2i.y += w.z*ti.y + w.w*tr.y;
        }
        s0 += g;
    }

    if (ty > 0) {
        sR1[ty-1][tx] = make_float4(a1r.x, a1r.y, a1i.x, a1i.y);
        sR2[ty-1][tx] = make_float4(a2r.x, a2r.y, a2i.x, a2i.y);
    }
    __syncthreads();
    if (ty == 0) {
        #pragma unroll
        for (int j = 0; j < SPLIT-1; ++j) {
            const float4 r1 = sR1[j][tx], r2 = sR2[j][tx];
            a1r.x += r1.x; a1r.y += r1.y; a1i.x += r1.z; a1i.y += r1.w;
            a2r.x += r2.x; a2r.y += r2.y; a2i.x += r2.z; a2i.y += r2.w;
        }
        const float Ps = exp10f(task[b*4] * 0.1f) * 0.5f;   // 10^(ti/10)/NMODES
        const int gi = b * SEQ + base + tx;
        g_E1r[gi] = make_float2(a1r.x*Ps, a1r.y*Ps);
        g_E1i[gi] = make_float2(a1i.x*Ps, a1i.y*Ps);
        g_Mr [gi] = make_float2(a2r.x*Ps, a2r.y*Ps);
        g_Mi [gi] = make_float2(a2i.x*Ps, a2i.y*Ps);
    }
}

// ---------------------------------------------------------------------------
// Stage 2: E2[l] = Ps * sum_s [ wf1_s * E1m[l-m] E[l-n] conj(E[l-m-n])
//                             + wf2_s * E[l-m]  E[l-n] conj(E1m[l-m-n]) ]
//          out   = E + 0.1*E1 + 0.01*E2,  sliced l in [50, 4046)
// ---------------------------------------------------------------------------
__global__ void __launch_bounds__(TILE*SPLIT)
stage2_kernel(const float2* __restrict__ Er, const float2* __restrict__ Ei,
              const float*  __restrict__ task,
              const float*  __restrict__ fcr, const float* __restrict__ fci,
              float4* __restrict__ out)
{
    __shared__ float2 sEr[SPOS], sEi[SPOS];
    __shared__ float2 sMr[SPOS], sMi[SPOS];
    __shared__ float4 sW[NS];                       // {fc1r, fc1i, fc2r, fc2i}
    __shared__ float4 sR[SPLIT-1][TILE];

    const int tile = blockIdx.x, b = blockIdx.y;
    const int tx = threadIdx.x, ty = threadIdx.y;
    const int tid = ty * TILE + tx;
    const int base = tile * TILE;
    const float2* Erb = Er + b * SEQ;
    const float2* Eib = Ei + b * SEQ;

    for (int i = tid; i < SPOS; i += TILE*SPLIT) {
        int p  = (base - HALO + i) & (SEQ - 1);
        int gp = b * SEQ + p;
        sEr[i] = Erb[p];
        sEi[i] = Eib[p];
        sMr[i] = g_Mr[gp];
        sMi[i] = g_Mi[gp];
    }
    for (int s = tid; s < NS; s += TILE*SPLIT)
        sW[s] = make_float4(fcr[s], fci[s], fcr[NS + s], fci[NS + s]);
    __syncthreads();

    const int li = tx + HALO;
    float2 fr = make_float2(0.f,0.f), fi = make_float2(0.f,0.f);

    int s0 = 0;
    #pragma unroll 1
    for (int mi = 0; mi < 51; ++mi) {
        const int m  = mi - 25;
        const int nm = c_NM[mi];
        const int g  = 2*nm + 1;
        const int lia = li - m;
        const float2 amr = sEr[lia], ami = sEi[lia];   // E[l-m]
        const float2 gmr = sMr[lia], gmi = sMi[lia];   // E1m[l-m]
        int lib = li  + nm - ty;
        int lic = lia + nm - ty;
        for (int k = ty; k < g; k += SPLIT, lib -= SPLIT, lic -= SPLIT) {
            const float2 br = sEr[lib], bi = sEi[lib];
            const float2 cr = sEr[lic], ci = sEi[lic];
            const float2 dr = sMr[lic], di = sMi[lic]; // E1m[l-m-n]
            float2 ur, ui, t1r, t1i, vr, vi, t2r, t2i;
            // t1 = (E1m[l-m]*b)*conj(c)
            ur.x = gmr.x*br.x - gmi.x*bi.x;  ur.y = gmr.y*br.y - gmi.y*bi.y;
            ui.x = gmr.x*bi.x + gmi.x*br.x;  ui.y = gmr.y*bi.y + gmi.y*br.y;
            t1r.x = ur.x*cr.x + ui.x*ci.x;   t1r.y = ur.y*cr.y + ui.y*ci.y;
            t1i.x = ui.x*cr.x - ur.x*ci.x;   t1i.y = ui.y*cr.y - ur.y*ci.y;
            // t2 = (E[l-m]*b)*conj(E1m[l-m-n])
            vr.x = amr.x*br.x - ami.x*bi.x;  vr.y = amr.y*br.y - ami.y*bi.y;
            vi.x = amr.x*bi.x + ami.x*br.x;  vi.y = amr.y*bi.y + ami.y*br.y;
            t2r.x = vr.x*dr.x + vi.x*di.x;   t2r.y = vr.y*dr.y + vi.y*di.y;
            t2i.x = vi.x*dr.x - vr.x*di.x;   t2i.y = vi.y*dr.y - vr.y*di.y;
            const float4 w = sW[s0 + k];
            fr.x += w.x*t1r.x - w.y*t1i.x + w.z*t2r.x - w.w*t2i.x;
            fr.y += w.x*t1r.y - w.y*t1i.y + w.z*t2r.y - w.w*t2i.y;
            fi.x += w.x*t1i.x + w.y*t1r.x + w.z*t2i.x + w.w*t2r.x;
            fi.y += w.x*t1i.y + w.y*t1r.y + w.z*t2i.y + w.w*t2r.y;
        }
        s0 += g;
    }

    if (ty > 0)
        sR[ty-1][tx] = make_float4(fr.x, fr.y, fi.x, fi.y);
    __syncthreads();
    if (ty == 0) {
        #pragma unroll
        for (int j = 0; j < SPLIT-1; ++j) {
            const float4 r = sR[j][tx];
            fr.x += r.x; fr.y += r.y; fi.x += r.z; fi.y += r.w;
        }
        const int l = base + tx;
        if (l >= NLW && l < SEQ - NLW) {
            const float Ps = exp10f(task[b*4] * 0.1f) * 0.5f;
            const int gi = b * SEQ + l;
            const float2 e1r = g_E1r[gi], e1i = g_E1i[gi];
            const float2 er = sEr[li], ei = sEi[li];
            const float g2 = 0.01f * Ps;
            float2 outr, outi;
            outr.x = er.x + 0.1f*e1r.x + g2*fr.x;
            outr.y = er.y + 0.1f*e1r.y + g2*fr.y;
            outi.x = ei.x + 0.1f*e1i.x + g2*fi.x;
            outi.y = ei.y + 0.1f*e1i.y + g2*fi.y;
            // out layout: [B, OUTL, NMODES, 2] -> {re0, im0, re1, im1}
            out[b * OUTL + (l - NLW)] = make_float4(outr.x, outi.x, outr.y, outi.y);
        }
    }
}

extern "C" void kernel_launch(void* const* d_in, const int* in_sizes, int n_in,
                              void* d_out, int out_size)
{
    const float2* Er  = (const float2*)d_in[0];  // E_real [B,SEQ,NMODES]
    const float2* Ei  = (const float2*)d_in[1];  // E_imag
    const float*  task= (const float*)d_in[2];   // task_info [B,4]
    const float*  w1r = (const float*)d_in[3];
    const float*  w1i = (const float*)d_in[4];
    const float*  w2r = (const float*)d_in[5];
    const float*  w2i = (const float*)d_in[6];
    const float*  fcr = (const float*)d_in[7];
    const float*  fci = (const float*)d_in[8];

    dim3 grid(SEQ / TILE, BATCH);
    dim3 blk(TILE, SPLIT);
    stage1_kernel<<<grid, blk>>>(Er, Ei, task, w1r, w1i, w2r, w2i);
    stage2_kernel<<<grid, blk>>>(Er, Ei, task, fcr, fci, (float4*)d_out);
}

// round 2
// speedup vs baseline: 1.3336x; 1.3336x over previous
#include <cuda_runtime.h>

#define SEQ    4096
#define BATCH  4
#define NLW    50
#define HALO   26                 // max |m+n| under |m*n|<=25
#define TILE   32
#define SPLIT  8
#define SPOS   (TILE + 2*HALO)    // 84
#define NS     449
#define OUTL   (SEQ - 2*NLW)      // 3996

typedef unsigned long long u64;

// ---------------- packed f32x2 helpers ----------------
__device__ __forceinline__ u64 fma2(u64 a, u64 b, u64 c) {
    u64 d; asm("fma.rn.f32x2 %0, %1, %2, %3;" : "=l"(d) : "l"(a), "l"(b), "l"(c)); return d;
}
__device__ __forceinline__ u64 mul2(u64 a, u64 b) {
    u64 d; asm("mul.rn.f32x2 %0, %1, %2;" : "=l"(d) : "l"(a), "l"(b)); return d;
}
__device__ __forceinline__ u64 sub2(u64 a, u64 b) {
    u64 d; asm("sub.rn.f32x2 %0, %1, %2;" : "=l"(d) : "l"(a), "l"(b)); return d;
}
__device__ __forceinline__ u64 add2(u64 a, u64 b) {
    u64 d; asm("add.rn.f32x2 %0, %1, %2;" : "=l"(d) : "l"(a), "l"(b)); return d;
}
__device__ __forceinline__ u64 packf2(float2 v) {              // {v.x lo, v.y hi}
    u64 d; asm("mov.b64 %0, {%1, %2};" : "=l"(d) : "f"(v.x), "f"(v.y)); return d;
}
__device__ __forceinline__ u64 pack2(float x) {                // duplicate
    u64 d; asm("mov.b64 %0, {%1, %1};" : "=l"(d) : "f"(x)); return d;
}
__device__ __forceinline__ float2 unpackf2(u64 v) {
    float2 f; asm("mov.b64 {%0, %1}, %2;" : "=f"(f.x), "=f"(f.y) : "l"(v)); return f;
}

// ---------------- compile-time sparse index schedule ----------------
// Flat s order = reference order: m = -25..25 outer, n = -nm..nm inner.
// Per-warp contiguous chunks: ty0 -> [0,57), ty>0 -> [57+(ty-1)*56, +56)
struct STab {
    int S0[52];   // prefix sums of group sizes
    int M[51];    // m value per group
    int NM[51];   // max |n| per group
    int CMI[8];   // starting group index for each warp chunk
    constexpr STab() : S0(), M(), NM(), CMI() {
        int s = 0;
        for (int mi = 0; mi < 51; ++mi) {
            int m = mi - 25;
            int nm = 0;
            for (int n = 1; n <= 25; ++n) { int p = m * n; if (p < 0) p = -p; if (p <= 25) nm = n; }
            if (m == 0) nm = 25;
            S0[mi] = s; M[mi] = m; NM[mi] = nm;
            s += 2 * nm + 1;
        }
        S0[51] = s;  // 449
        for (int t = 0; t < 8; ++t) {
            int sb = t * 56 + (t ? 1 : 0);
            int k = 0;
            while (S0[k + 1] <= sb) ++k;
            CMI[t] = k;
        }
    }
};
__constant__ STab c_tab = STab();

// weight record: 32B, two LDS.128
struct __align__(16) WR { ulonglong2 a, b; };

// scratch (Ps-scaled), packed mode-pairs
__device__ u64 g_E1r[BATCH * SEQ];
__device__ u64 g_E1i[BATCH * SEQ];
__device__ u64 g_Mr [BATCH * SEQ];
__device__ u64 g_Mi [BATCH * SEQ];

// ---------------------------------------------------------------------------
// Stage 1
// ---------------------------------------------------------------------------
__global__ void __launch_bounds__(TILE * SPLIT)
stage1_kernel(const float2* __restrict__ Er, const float2* __restrict__ Ei,
              const float*  __restrict__ task,
              const float*  __restrict__ w1r, const float* __restrict__ w1i,
              const float*  __restrict__ w2r, const float* __restrict__ w2i)
{
    __shared__ ulonglong2 sE[SPOS];        // {er2, ei2}
    __shared__ WR sW[NS];                  // {w1r2,w1i2, w2r2,w2i2}
    __shared__ ulonglong2 sR1r[SPLIT - 1][TILE]; // {a1r,a1i}
    __shared__ ulonglong2 sR2r[SPLIT - 1][TILE]; // {a2r,a2i}

    const int tile = blockIdx.x, b = blockIdx.y;
    const int tx = threadIdx.x, ty = threadIdx.y;
    const int tid = ty * TILE + tx;
    const int base = tile * TILE;
    const float2* Erb = Er + b * SEQ;
    const float2* Eib = Ei + b * SEQ;

    for (int i = tid; i < SPOS; i += TILE * SPLIT) {
        int p = (base - HALO + i) & (SEQ - 1);
        sE[i] = make_ulonglong2(packf2(Erb[p]), packf2(Eib[p]));
    }
    for (int s = tid; s < NS; s += TILE * SPLIT) {
        WR w;
        w.a = make_ulonglong2(pack2(w1r[s]), pack2(w1i[s]));
        w.b = make_ulonglong2(pack2(w2r[s]), pack2(w2i[s]));
        sW[s] = w;
    }
    __syncthreads();

    const int li = tx + HALO;
    u64 a1r = 0, a1i = 0, a2r = 0, a2i = 0;
    const u64 z = 0;

    const int sBeg = ty * 56 + (ty ? 1 : 0);
    const int sEnd = sBeg + (ty ? 56 : 57);
    int mi = c_tab.CMI[ty];
    int s = sBeg;
    while (s < sEnd) {
        const int m  = c_tab.M[mi];
        const int s0 = c_tab.S0[mi];
        const int nm = c_tab.NM[mi];
        const int kEnd = min(c_tab.S0[mi + 1], sEnd);
        const ulonglong2 av = sE[li - m];
        int ib = li + nm - (s - s0);
        int ic = ib - m;
        #pragma unroll 1
        for (; s < kEnd; ++s, --ib, --ic) {
            const ulonglong2 bv = sE[ib];
            const ulonglong2 cv = sE[ic];
            // u = a*b
            const u64 ur = sub2(mul2(av.x, bv.x), mul2(av.y, bv.y));
            const u64 ui = fma2(av.x, bv.y, mul2(av.y, bv.x));
            // t = u*conj(c)
            const u64 tr = fma2(ui, cv.y, mul2(ur, cv.x));
            const u64 ti = sub2(mul2(ui, cv.x), mul2(ur, cv.y));
            const u64 nti = sub2(z, ti);
            const WR w = sW[s];
            a1r = fma2(w.a.x, tr, a1r);  a1r = fma2(w.a.y, nti, a1r);
            a1i = fma2(w.a.x, ti, a1i);  a1i = fma2(w.a.y, tr,  a1i);
            a2r = fma2(w.b.x, tr, a2r);  a2r = fma2(w.b.y, nti, a2r);
            a2i = fma2(w.b.x, ti, a2i);  a2i = fma2(w.b.y, tr,  a2i);
        }
        ++mi;
    }

    if (ty > 0) {
        sR1r[ty - 1][tx] = make_ulonglong2(a1r, a1i);
        sR2r[ty - 1][tx] = make_ulonglong2(a2r, a2i);
    }
    __syncthreads();
    if (ty == 0) {
        #pragma unroll
        for (int j = 0; j < SPLIT - 1; ++j) {
            const ulonglong2 r1 = sR1r[j][tx], r2 = sR2r[j][tx];
            a1r = add2(a1r, r1.x);  a1i = add2(a1i, r1.y);
            a2r = add2(a2r, r2.x);  a2i = add2(a2i, r2.y);
        }
        const u64 Ps = pack2(exp10f(task[b * 4] * 0.1f) * 0.5f);
        const int gi = b * SEQ + base + tx;
        g_E1r[gi] = mul2(a1r, Ps);
        g_E1i[gi] = mul2(a1i, Ps);
        g_Mr [gi] = mul2(a2r, Ps);
        g_Mi [gi] = mul2(a2i, Ps);
    }
}

// ---------------------------------------------------------------------------
// Stage 2
// ---------------------------------------------------------------------------
__global__ void __launch_bounds__(TILE * SPLIT)
stage2_kernel(const float2* __restrict__ Er, const float2* __restrict__ Ei,
              const float*  __restrict__ task,
              const float*  __restrict__ fcr, const float* __restrict__ fci,
              float4* __restrict__ out)
{
    __shared__ ulonglong2 sE[SPOS];
    __shared__ ulonglong2 sM[SPOS];        // {E1m_r2, E1m_i2}
    __shared__ WR sW[NS];                  // {f1r2,f1i2, f2r2,f2i2}
    __shared__ ulonglong2 sR[SPLIT - 1][TILE];

    const int tile = blockIdx.x, b = blockIdx.y;
    const int tx = threadIdx.x, ty = threadIdx.y;
    const int tid = ty * TILE + tx;
    const int base = tile * TILE;
    const float2* Erb = Er + b * SEQ;
    const float2* Eib = Ei + b * SEQ;

    for (int i = tid; i < SPOS; i += TILE * SPLIT) {
        int p  = (base - HALO + i) & (SEQ - 1);
        int gp = b * SEQ + p;
        sE[i] = make_ulonglong2(packf2(Erb[p]), packf2(Eib[p]));
        sM[i] = make_ulonglong2(g_Mr[gp], g_Mi[gp]);
    }
    for (int s = tid; s < NS; s += TILE * SPLIT) {
        WR w;
        w.a = make_ulonglong2(pack2(fcr[s]), pack2(fci[s]));
        w.b = make_ulonglong2(pack2(fcr[NS + s]), pack2(fci[NS + s]));
        sW[s] = w;
    }
    __syncthreads();

    const int li = tx + HALO;
    u64 fr = 0, fi = 0;
    const u64 z = 0;

    const int sBeg = ty * 56 + (ty ? 1 : 0);
    const int sEnd = sBeg + (ty ? 56 : 57);
    int mi = c_tab.CMI[ty];
    int s = sBeg;
    while (s < sEnd) {
        const int m  = c_tab.M[mi];
        const int s0 = c_tab.S0[mi];
        const int nm = c_tab.NM[mi];
        const int kEnd = min(c_tab.S0[mi + 1], sEnd);
        const int lia = li - m;
        const ulonglong2 av = sE[lia];     // E[l-m]
        const ulonglong2 gv = sM[lia];     // E1m[l-m]
        int ib = li + nm - (s - s0);
        int ic = ib - m;
        #pragma unroll 1
        for (; s < kEnd; ++s, --ib, --ic) {
            const ulonglong2 bv = sE[ib];
            const ulonglong2 cv = sE[ic];
            const ulonglong2 dv = sM[ic];  // E1m[l-m-n]
            // t1 = (E1m[l-m] * b) * conj(c)
            const u64 ur  = sub2(mul2(gv.x, bv.x), mul2(gv.y, bv.y));
            const u64 ui  = fma2(gv.x, bv.y, mul2(gv.y, bv.x));
            const u64 t1r = fma2(ui, cv.y, mul2(ur, cv.x));
            const u64 t1i = sub2(mul2(ui, cv.x), mul2(ur, cv.y));
            // t2 = (E[l-m] * b) * conj(E1m[l-m-n])
            const u64 vr  = sub2(mul2(av.x, bv.x), mul2(av.y, bv.y));
            const u64 vi  = fma2(av.x, bv.y, mul2(av.y, bv.x));
            const u64 t2r = fma2(vi, dv.y, mul2(vr, dv.x));
            const u64 t2i = sub2(mul2(vi, dv.x), mul2(vr, dv.y));
            const u64 nt1i = sub2(z, t1i);
            const u64 nt2i = sub2(z, t2i);
            const WR w = sW[s];
            fr = fma2(w.a.x, t1r, fr);  fr = fma2(w.a.y, nt1i, fr);
            fr = fma2(w.b.x, t2r, fr);  fr = fma2(w.b.y, nt2i, fr);
            fi = fma2(w.a.x, t1i, fi);  fi = fma2(w.a.y, t1r, fi);
            fi = fma2(w.b.x, t2i, fi);  fi = fma2(w.b.y, t2r, fi);
        }
        ++mi;
    }

    if (ty > 0)
        sR[ty - 1][tx] = make_ulonglong2(fr, fi);
    __syncthreads();
    if (ty == 0) {
        #pragma unroll
        for (int j = 0; j < SPLIT - 1; ++j) {
            const ulonglong2 r = sR[j][tx];
            fr = add2(fr, r.x);  fi = add2(fi, r.y);
        }
        const int l = base + tx;
        if (l >= NLW && l < SEQ - NLW) {
            const float Psf = exp10f(task[b * 4] * 0.1f) * 0.5f;
            const u64 g2 = pack2(0.01f * Psf);
            const int gi = b * SEQ + l;
            const ulonglong2 ev = sE[li];
            const u64 c01 = pack2(0.1f);
            u64 outr = fma2(g2, fr, fma2(c01, g_E1r[gi], ev.x));
            u64 outi = fma2(g2, fi, fma2(c01, g_E1i[gi], ev.y));
            const float2 orr = unpackf2(outr);
            const float2 oii = unpackf2(outi);
            // out layout per l: {re0, im0, re1, im1}
            out[b * OUTL + (l - NLW)] = make_float4(orr.x, oii.x, orr.y, oii.y);
        }
    }
}

extern "C" void kernel_launch(void* const* d_in, const int* in_sizes, int n_in,
                              void* d_out, int out_size)
{
    const float2* Er   = (const float2*)d_in[0];
    const float2* Ei   = (const float2*)d_in[1];
    const float*  task = (const float*)d_in[2];
    const float*  w1r  = (const float*)d_in[3];
    const float*  w1i  = (const float*)d_in[4];
    const float*  w2r  = (const float*)d_in[5];
    const float*  w2i  = (const float*)d_in[6];
    const float*  fcr  = (const float*)d_in[7];
    const float*  fci  = (const float*)d_in[8];

    dim3 grid(SEQ / TILE, BATCH);
    dim3 blk(TILE, SPLIT);
    stage1_kernel<<<grid, blk>>>(Er, Ei, task, w1r, w1i, w2r, w2i);
    stage2_kernel<<<grid, blk>>>(Er, Ei, task, fcr, fci, (float4*)d_out);
}